// round 16
// baseline (speedup 1.0000x reference)
#include <cuda_runtime.h>
#include <stdint.h>

#define BB   8
#define NN   8192
#define CIN  64
#define COUT 128
#define MM   2048
#define KNN  16
#define ROWS (BB*NN)            // 65536
#define Y_SIZE ((size_t)BB*MM*COUT)

#define FPS_THREADS 256
#define FPS_PT      16          // points per thread (256*16 = 4096 = half batch)

// fused-kernel block layout (waiters only depend on LOWER block ids).
// Launched with cluster dims (2,1,1): every section range is even-aligned so
// each cluster pairs two SAME-role blocks; (bn2, dummy) share the odd pair.
#define NB_FPS    (BB*2)                    // 0..15    : FPS (8 clusters x 2 CTAs)
#define GEMM_BASE NB_FPS                    // 16..527  : GEMM (512)
#define NB_GEMM   (ROWS/128)                // 512
#define BN1_BASE  (GEMM_BASE + NB_GEMM)     // 528..783 : bnstat1 (256)
#define NB_BN1    256
#define BN2_BASE  (BN1_BASE + NB_BN1)       // 784      : bnstat2 ; 785 dummy
#define KNN_BASE  (BN2_BASE + 2)            // 786..    : kNN+gather (2048)
#define NB_KNN    (BB*(MM/8))
#define FUSED_BLOCKS (KNN_BASE + NB_KNN)    // 2834 (even)

// ---------------- scratch (static device globals; no allocations) ----------------
__device__ float g_h[(size_t)ROWS*COUT];     // raw h = x @ W^T  (32 MB)
__device__ float g_psum[256*COUT];
__device__ float g_psq [256*COUT];
__device__ float g_scale[COUT];
__device__ float g_shift[COUT];
__device__ int   g_prog[BB];                 // FPS progress       (reset each call)
__device__ int   g_gemm_cnt;                 // finished gemm blks (reset each call)
__device__ int   g_bn1_cnt;                  // finished bn1 blks  (reset each call)
__device__ int   g_scale_ready;              // bn2 published      (reset each call)

// -------- packed f32x2 helpers (sm_100+; per-lane bits == scalar rn ops) --------
#define ADD_F32X2(out, a, b) \
    asm("add.rn.f32x2 %0, %1, %2;" : "=l"(out) : "l"(a), "l"(b))
#define MUL_F32X2(out, a, b) \
    asm("mul.rn.f32x2 %0, %1, %2;" : "=l"(out) : "l"(a), "l"(b))
#define PACK_F32X2(out, lo, hi) \
    asm("mov.b64 %0, {%1, %2};" : "=l"(out) : "f"(lo), "f"(hi))
#define UNPACK_F32X2(lo, hi, in) \
    asm("mov.b64 {%0, %1}, %2;" : "=f"(lo), "=f"(hi) : "l"(in))

#define REDUX_MAX_U32(out, in) \
    asm("redux.sync.max.u32 %0, %1, 0xffffffff;" : "=r"(out) : "r"(in))
#define REDUX_MIN_U32(out, in) \
    asm("redux.sync.min.u32 %0, %1, 0xffffffff;" : "=r"(out) : "r"(in))

__device__ __forceinline__ int ld_acq(const int* p) {
    int v;
    asm volatile("ld.acquire.gpu.global.s32 %0, [%1];" : "=r"(v) : "l"(p));
    return v;
}
__device__ __forceinline__ void st_rel(int* p, int v) {
    asm volatile("st.release.gpu.global.s32 [%0], %1;" :: "l"(p), "r"(v) : "memory");
}
__device__ __forceinline__ uint32_t smem_u32(const void* p) {
    uint32_t a;
    asm("{ .reg .u64 t; cvta.to.shared.u64 t, %1; cvt.u32.u64 %0, t; }"
        : "=r"(a) : "l"(p));
    return a;
}
__device__ __forceinline__ unsigned f2key(float d) {
    unsigned u = __float_as_uint(d);
    return u ^ ((u >> 31) ? 0xFFFFFFFFu : 0x80000000u);
}

// =============================== FPS ===============================
// 8 clusters x 2 CTAs (blocks 0..15): batch = bid>>1, rank = bid&1. Each CTA
// owns HALF the points in registers (16/thread, packed f32x2; distance bits
// identical to XLA — separate rn ops, trajectory bit-exact since R3) and the
// FULL point table in smem for winner coord lookup.
// Per iteration:
//   in-CTA  : warp redux(max val)+redux(min idx); leaders STS (parity); bar1;
//             all warps redux 8 slots -> (bval,bidx); key=(val<<32)|(NN-1-idx).
//   exchange: tid0 st.shared::cluster.b64 key into PEER xslot[j&1] + ONE
//             remote mbarrier.arrive.release.cluster; then try_wait local
//             mbar[j&1] (parity ((j-1)>>1)&1); bar2.
//   combine : win = max(own key, peer key)  (max key == max val, tie -> lowest
//             global index since low half = NN-1-idx); coords via local LDS.
// WAR safety: depth-2 slots/mbars; writer of slot[b] at j+2 passed wait j+1
// which required my arrive j+1 which follows my bar1 j+1 which follows my
// read of slot[b] at j. mbarriers re-initialized every launch.
__device__ void fps_section(const float* __restrict__ p1, float* __restrict__ p2out,
                            float* sm) {
    float* px = sm; float* py = sm + NN; float* pz = sm + 2*NN;
    __shared__ __align__(8) unsigned long long xslot[2];   // peer's record
    __shared__ __align__(8) unsigned long long mbar[2];
    __shared__ unsigned swv[2][8], swi[2][8];
    const int bid = blockIdx.x;
    const int b    = bid >> 1;
    const int rank = bid & 1;
    const int tid = threadIdx.x;
    const int lane = tid & 31;
    const int wid  = tid >> 5;
    const float* p = p1 + (size_t)b*NN*3;
    const int pbase = rank*(NN/2) + tid*FPS_PT;

    const uint32_t bar0 = smem_u32(&mbar[0]);
    const uint32_t bar1a = smem_u32(&mbar[1]);
    const uint32_t slot0 = smem_u32(&xslot[0]);
    const uint32_t slot1 = smem_u32(&xslot[1]);
    if (tid == 0) {
        asm volatile("mbarrier.init.shared.b64 [%0], 1;" :: "r"(bar0) : "memory");
        asm volatile("mbarrier.init.shared.b64 [%0], 1;" :: "r"(bar1a) : "memory");
    }

    // full point table (both halves) into smem; packed regs for OWN half only
    for (int i = tid; i < NN*3; i += FPS_THREADS) {
        float v = p[i];
        int pt = i / 3, d = i - pt*3;
        (d == 0 ? px : (d == 1 ? py : pz))[pt] = v;
    }
    float MD[FPS_PT];
    unsigned long long Xp[FPS_PT/2], Yp[FPS_PT/2], Zp[FPS_PT/2];
    {
        float buf[FPS_PT*3];
        const float4* pv = (const float4*)(p + (size_t)pbase*3);
        #pragma unroll
        for (int i = 0; i < FPS_PT*3/4; i++) {
            float4 v = pv[i];
            buf[i*4+0]=v.x; buf[i*4+1]=v.y; buf[i*4+2]=v.z; buf[i*4+3]=v.w;
        }
        #pragma unroll
        for (int k = 0; k < FPS_PT; k++) MD[k] = 1e10f;
        #pragma unroll
        for (int i = 0; i < FPS_PT/2; i++) {
            PACK_F32X2(Xp[i], buf[6*i+0], buf[6*i+3]);
            PACK_F32X2(Yp[i], buf[6*i+1], buf[6*i+4]);
            PACK_F32X2(Zp[i], buf[6*i+2], buf[6*i+5]);
        }
    }
    float lx = p[0], ly = p[1], lz = p[2];
    if (rank == 0 && tid == 0) {
        size_t o0 = (size_t)b*MM*3;
        p2out[o0+0]=lx; p2out[o0+1]=ly; p2out[o0+2]=lz;
        st_rel(&g_prog[b], 0);
    }
    __syncthreads();
    // both CTAs' mbarriers + tables ready before any remote arrive
    asm volatile("barrier.cluster.arrive.aligned;" ::: "memory");
    asm volatile("barrier.cluster.wait.aligned;" ::: "memory");

    for (int j = 1; j < MM; j++) {
        float nlx = -lx, nly = -ly, nlz = -lz;
        unsigned long long nlx2, nly2, nlz2;
        PACK_F32X2(nlx2, nlx, nlx);
        PACK_F32X2(nly2, nly, nly);
        PACK_F32X2(nlz2, nlz, nlz);

        #pragma unroll
        for (int i = 0; i < FPS_PT/2; i++) {
            unsigned long long dx, dy, dz, sx, sy, sz, s, d;
            ADD_F32X2(dx, Xp[i], nlx2);          // X + (-lx) == X - lx (bitwise)
            ADD_F32X2(dy, Yp[i], nly2);
            ADD_F32X2(dz, Zp[i], nlz2);
            MUL_F32X2(sx, dx, dx);
            MUL_F32X2(sy, dy, dy);
            MUL_F32X2(sz, dz, dz);
            ADD_F32X2(s,  sx, sy);               // (dx^2+dy^2)
            ADD_F32X2(d,  s,  sz);               // ... + dz^2
            float d0, d1; UNPACK_F32X2(d0, d1, d);
            MD[2*i]   = fminf(MD[2*i],   d0);
            MD[2*i+1] = fminf(MD[2*i+1], d1);
        }

        // thread-local max value (tree), then lowest matching k
        float t[FPS_PT/2];
        #pragma unroll
        for (int k = 0; k < FPS_PT/2; k++) t[k] = fmaxf(MD[2*k], MD[2*k+1]);
        #pragma unroll
        for (int w = FPS_PT/4; w >= 1; w >>= 1)
            #pragma unroll
            for (int k = 0; k < w; k++) t[k] = fmaxf(t[k], t[k+w]);
        float bv = t[0];
        int bi = FPS_PT-1;
        #pragma unroll
        for (int k = FPS_PT-2; k >= 0; k--) if (MD[k] == bv) bi = k;
        unsigned bvb = __float_as_uint(bv);      // dist >= 0: float order == u32 order

        // warp reduce: max value, then min index among ties
        unsigned wmax; REDUX_MAX_U32(wmax, bvb);
        unsigned cand = (bvb == wmax) ? (unsigned)(pbase + bi) : 0xFFFFFFFFu;
        unsigned widx; REDUX_MIN_U32(widx, cand);
        if (lane == 0) { swv[j & 1][wid] = wmax; swi[j & 1][wid] = widx; }
        __syncthreads();                          // bar1

        // CTA reduce (all warps redundantly over 8 leader slots)
        unsigned v  = (lane < 8) ? swv[j & 1][lane] : 0u;
        unsigned bval; REDUX_MAX_U32(bval, v);
        unsigned ci = (lane < 8 && v == bval) ? swi[j & 1][lane] : 0xFFFFFFFFu;
        unsigned bidx; REDUX_MIN_U32(bidx, ci);   // CTA winner global index

        unsigned long long key =
            ((unsigned long long)bval << 32) | (unsigned)(NN-1-(int)bidx);

        // exchange: tid0 publishes key to PEER, arrives on PEER's mbar, waits local
        if (tid == 0) {
            uint32_t myslot = (j & 1) ? slot1 : slot0;
            uint32_t mybar  = (j & 1) ? bar1a : bar0;
            uint32_t rslot, rbar;
            asm("mapa.shared::cluster.u32 %0, %1, %2;" : "=r"(rslot) : "r"(myslot), "r"(rank^1));
            asm("mapa.shared::cluster.u32 %0, %1, %2;" : "=r"(rbar)  : "r"(mybar),  "r"(rank^1));
            asm volatile("st.shared::cluster.u64 [%0], %1;"
                         :: "r"(rslot), "l"(key) : "memory");
            asm volatile("mbarrier.arrive.release.cluster.shared::cluster.b64 _, [%0];"
                         :: "r"(rbar) : "memory");
            unsigned parity = (unsigned)(((j - 1) >> 1) & 1);
            asm volatile(
                "{\n\t.reg .pred P1;\n\t"
                "WAIT_%=:\n\t"
                "mbarrier.try_wait.parity.acquire.cluster.shared::cta.b64 P1, [%0], %1;\n\t"
                "@P1 bra.uni DONE_%=;\n\t"
                "bra.uni WAIT_%=;\n\t"
                "DONE_%=:\n\t}"
                :: "r"(mybar), "r"(parity) : "memory");
        }
        __syncthreads();                          // bar2

        // combine: max key wins; tie -> larger (NN-1-idx) = lower index
        unsigned long long pkey = xslot[j & 1];
        unsigned long long win = (pkey > key) ? pkey : key;
        int idx = (NN-1) - (int)(win & 0xFFFFFFFFull);

        lx = px[idx]; ly = py[idx]; lz = pz[idx];
        if (rank == 0 && tid == 0) {
            size_t o2 = (size_t)(b*MM + j)*3;
            p2out[o2] = lx; p2out[o2+1] = ly; p2out[o2+2] = lz;
            st_rel(&g_prog[b], j);
        }
    }
}

// ============ GEMM section (exact fp32, bit-matches cuBLAS SGEMM chain) ============
__device__ void gemm_section(const float* __restrict__ x, const float* __restrict__ W,
                             float* sm) {
    float* xs = sm;                // [128][65] padded
    float* ws = sm + 128*65;       // [64][128] = W^T
    const int tid = threadIdx.x;
    const size_t rb = (size_t)(blockIdx.x - GEMM_BASE) * 128;
    const float* gx = x + rb*CIN;

    for (int i = tid; i < 128*CIN; i += 256) {
        int r = i >> 6, c = i & 63;
        xs[r*65 + c] = gx[i];
    }
    for (int i = tid; i < COUT*CIN; i += 256) {
        int o = i >> 6, c = i & 63;
        ws[c*COUT + o] = W[i];
    }
    __syncthreads();

    const int tx = tid & 15, ty = tid >> 4;
    const int r0 = ty*8, o0 = tx*8;
    float acc[8][8];
    #pragma unroll
    for (int i = 0; i < 8; i++)
        #pragma unroll
        for (int j = 0; j < 8; j++) acc[i][j] = 0.f;

    for (int c = 0; c < CIN; c++) {
        float a[8];
        #pragma unroll
        for (int i = 0; i < 8; i++) a[i] = xs[(r0+i)*65 + c];
        float4 b0 = *(const float4*)&ws[c*COUT + o0];
        float4 b1 = *(const float4*)&ws[c*COUT + o0 + 4];
        float bb[8] = {b0.x,b0.y,b0.z,b0.w,b1.x,b1.y,b1.z,b1.w};
        #pragma unroll
        for (int i = 0; i < 8; i++)
            #pragma unroll
            for (int j = 0; j < 8; j++) acc[i][j] = __fmaf_rn(a[i], bb[j], acc[i][j]);
    }
    #pragma unroll
    for (int i = 0; i < 8; i++) {
        float* out = &g_h[(rb + r0 + i)*COUT + o0];
        *(float4*)out       = make_float4(acc[i][0],acc[i][1],acc[i][2],acc[i][3]);
        *(float4*)(out + 4) = make_float4(acc[i][4],acc[i][5],acc[i][6],acc[i][7]);
    }
    __threadfence();
    __syncthreads();
    if (tid == 0) atomicAdd(&g_gemm_cnt, 1);
}

// ============ bnstat1 section (waits for all gemm blocks) ============
__device__ void bn1_section() {
    __shared__ float cs[128], cq[128];
    const int tid = threadIdx.x;
    if (tid == 0) { while (ld_acq(&g_gemm_cnt) < NB_GEMM) __nanosleep(256); }
    __syncthreads();

    const int blk = blockIdx.x - BN1_BASE;       // 0..255
    const int c = tid & 127;
    const int half = tid >> 7;                   // 0/1
    const float* base = g_h + ((size_t)blk*256 + (size_t)half*128)*COUT;
    float s = 0.f, q = 0.f;
    for (int r = 0; r < 128; r++) {
        float v = base[(size_t)r*COUT + c];
        s += v; q = __fmaf_rn(v, v, q);
    }
    if (half) { cs[c] = s; cq[c] = q; }
    __syncthreads();
    if (!half) {
        g_psum[blk*COUT + c] = s + cs[c];
        g_psq [blk*COUT + c] = q + cq[c];
    }
    __threadfence();
    __syncthreads();
    if (tid == 0) atomicAdd(&g_bn1_cnt, 1);
}

// ============ bnstat2 section (single block; publishes scale_ready) ============
__device__ void bn2_section(const float* __restrict__ gamma, const float* __restrict__ beta) {
    __shared__ double s0[128], q0[128];
    const int tid = threadIdx.x;
    if (tid == 0) { while (ld_acq(&g_bn1_cnt) < NB_BN1) __nanosleep(256); }
    __syncthreads();

    const int c = tid & 127, half = tid >> 7;
    double s = 0.0, q = 0.0;
    for (int i = 0; i < 128; i++) {
        int blk = half*128 + i;
        s += (double)g_psum[blk*COUT + c];
        q += (double)g_psq [blk*COUT + c];
    }
    if (half) { s0[c] = s; q0[c] = q; }
    __syncthreads();
    if (!half) {
        double S = s + s0[c], Q = q + q0[c];
        double mean = S / (double)ROWS;
        double var  = Q / (double)ROWS - mean*mean;
        double inv  = 1.0 / sqrt(var + 1e-5);
        float sc = (float)inv * gamma[c];
        g_scale[c] = sc;
        g_shift[c] = __fmaf_rn(-(float)mean, sc, beta[c]);
    }
    __threadfence();
    __syncthreads();
    if (tid == 0) st_rel(&g_scale_ready, 1);
}

// ============ kNN + inline gather section ============
__device__ void knn_section(const float* __restrict__ p1, const float* __restrict__ p2,
                            float* __restrict__ y, float* sm) {
    float* px = sm; float* py = sm+NN; float* pz = sm+2*NN; float* s1 = sm+3*NN;
    const int tid = threadIdx.x;
    const int q  = blockIdx.x - KNN_BASE;        // 0..2047
    const int b  = q & 7;                        // batch-interleaved
    const int mg = q >> 3;
    const float* p = p1 + (size_t)b*NN*3;

    // independent smem prep overlaps the wait
    for (int i = tid; i < NN*3; i += 256) {
        float v = p[i];
        int pt = i / 3, d = i - pt*3;
        (d == 0 ? px : (d == 1 ? py : pz))[pt] = v;
    }
    __syncthreads();
    for (int i = tid; i < NN; i += 256)
        s1[i] = __fadd_rn(__fadd_rn(__fmul_rn(px[i],px[i]), __fmul_rn(py[i],py[i])), __fmul_rn(pz[i],pz[i]));

    // wait until FPS published query mg*8+7 for this batch
    if (tid == 0) {
        const int need = mg*8 + 7;
        while (ld_acq(&g_prog[b]) < need) __nanosleep(128);
    }
    __syncthreads();

    const int w = tid >> 5, lane = tid & 31;
    const int m = mg*8 + w;
    const size_t qi = (size_t)b*MM + m;
    // p2 written by FPS blocks this launch -> read via L2 (__ldcg)
    const float qx = __ldcg(&p2[qi*3]);
    const float qy = __ldcg(&p2[qi*3+1]);
    const float qz = __ldcg(&p2[qi*3+2]);
    const float s2 = __fadd_rn(__fadd_rn(__fmul_rn(qx,qx), __fmul_rn(qy,qy)), __fmul_rn(qz,qz));

    const unsigned long long INITK =
        ((unsigned long long)0xFF7FFFFFu << 32) | 0xFFFFFFFFu;
    unsigned long long bk[KNN];
    #pragma unroll
    for (int k = 0; k < KNN; k++) bk[k] = INITK;
    float thr = 3.4e38f;

    for (int i = lane; i < NN; i += 32) {
        float dot = __fmaf_rn(pz[i], qz, __fmaf_rn(py[i], qy, __fmul_rn(px[i], qx)));
        float d   = __fadd_rn(__fsub_rn(s2, __fmul_rn(2.0f, dot)), s1[i]);
        if (d < thr) {   // equal -> keep earlier index (top_k stability)
            unsigned long long nk = ((unsigned long long)f2key(d) << 32) | (unsigned)i;
            unsigned long long mk = 0; int mp = 0;
            #pragma unroll
            for (int k = 0; k < KNN; k++) if (bk[k] > mk) { mk = bk[k]; mp = k; }
            #pragma unroll
            for (int k = 0; k < KNN; k++) if (k == mp) bk[k] = nk;
            mk = 0;
            #pragma unroll
            for (int k = 0; k < KNN; k++) if (bk[k] > mk) mk = bk[k];
            unsigned hv = (unsigned)(mk >> 32);
            hv = (hv & 0x80000000u) ? (hv ^ 0x80000000u) : ~hv;
            thr = __uint_as_float(hv);
        }
    }

    unsigned long long res = 0;
    for (int r = 0; r < KNN; r++) {
        unsigned long long lm = 0xFFFFFFFFFFFFFFFFull;
        #pragma unroll
        for (int k = 0; k < KNN; k++) if (bk[k] < lm) lm = bk[k];
        unsigned long long wm = lm;
        #pragma unroll
        for (int o = 16; o; o >>= 1) {
            unsigned long long t = __shfl_xor_sync(0xffffffffu, wm, o);
            if (t < wm) wm = t;
        }
        if (lm == wm) {
            #pragma unroll
            for (int k = 0; k < KNN; k++) if (bk[k] == wm) bk[k] = 0xFFFFFFFFFFFFFFFFull;
        }
        if (lane == r) res = wm;
    }
    unsigned resi = (unsigned)(res & 0xFFFFFFFFu);   // lane r < 16: r-th neighbor

    // ---- inline gather + BN + ReLU + max (neighbors stay in registers) ----
    if (tid == 0) { while (ld_acq(&g_scale_ready) == 0) __nanosleep(128); }
    __syncthreads();

    const float4 sc = __ldcg((const float4*)&g_scale[lane*4]);
    const float4 sh = __ldcg((const float4*)&g_shift[lane*4]);
    const float* hb = g_h + (size_t)b*NN*COUT;

    float4 acc = make_float4(-3.4e38f,-3.4e38f,-3.4e38f,-3.4e38f);
    #pragma unroll
    for (int k = 0; k < KNN; k++) {
        unsigned n = __shfl_sync(0xffffffffu, resi, k);
        float4 v = *(const float4*)&hb[(size_t)n*COUT + lane*4];
        float f;
        f = fmaxf(__fmaf_rn(v.x, sc.x, sh.x), 0.f); acc.x = fmaxf(acc.x, f);
        f = fmaxf(__fmaf_rn(v.y, sc.y, sh.y), 0.f); acc.y = fmaxf(acc.y, f);
        f = fmaxf(__fmaf_rn(v.z, sc.z, sh.z), 0.f); acc.z = fmaxf(acc.z, f);
        f = fmaxf(__fmaf_rn(v.w, sc.w, sh.w), 0.f); acc.w = fmaxf(acc.w, f);
    }
    *(float4*)&y[qi*COUT + lane*4] = acc;
}

// ================= fused kernel: everything in one launch =================
__global__ void __launch_bounds__(256, 1) __cluster_dims__(2, 1, 1)
fused_kernel(const float* __restrict__ x, const float* __restrict__ p1,
             const float* __restrict__ W, const float* __restrict__ gamma,
             const float* __restrict__ beta, float* __restrict__ y,
             float* __restrict__ p2out) {
    extern __shared__ float sm[];
    const int bid = blockIdx.x;
    if (bid < NB_FPS)              fps_section(p1, p2out, sm);
    else if (bid < BN1_BASE)       gemm_section(x, W, sm);
    else if (bid < BN2_BASE)       bn1_section();
    else if (bid == BN2_BASE)      bn2_section(gamma, beta);
    else if (bid == BN2_BASE + 1)  return;                      // dummy pair
    else                           knn_section(p1, p2out, y, sm);
}

// ================= per-call state reset (runs before fused, in-stream) =================
__global__ void reset_kernel() {
    const int t = threadIdx.x;
    if (t < BB) g_prog[t] = -1;
    if (t == 8)  g_gemm_cnt = 0;
    if (t == 9)  g_bn1_cnt = 0;
    if (t == 10) g_scale_ready = 0;
}

// =============================== launch ===============================
extern "C" void kernel_launch(void* const* d_in, const int* in_sizes, int n_in,
                              void* d_out, int out_size) {
    const float* x     = (const float*)d_in[0];
    const float* p1    = (const float*)d_in[1];
    const float* W     = (const float*)d_in[2];
    const float* gamma = (const float*)d_in[3];
    const float* beta  = (const float*)d_in[4];
    float* y  = (float*)d_out;
    float* p2 = y + Y_SIZE;

    const int FUSED_SMEM = 4*NN*4;         // 128 KB (knn: 4 arrays; fps: 3; gemm: 66KB)

    cudaFuncSetAttribute(fused_kernel, cudaFuncAttributeMaxDynamicSharedMemorySize, FUSED_SMEM);

    reset_kernel<<<1, 32>>>();
    fused_kernel<<<FUSED_BLOCKS, 256, FUSED_SMEM>>>(x, p1, W, gamma, beta, y, p2);
}

// round 17
// speedup vs baseline: 1.0682x; 1.0682x over previous
#include <cuda_runtime.h>
#include <stdint.h>

#define BB   8
#define NN   8192
#define CIN  64
#define COUT 128
#define MM   2048
#define KNN  16
#define ROWS (BB*NN)            // 65536
#define Y_SIZE ((size_t)BB*MM*COUT)

#define FPS_THREADS 256
#define FPS_PT      32          // points per thread (256*32 = 8192)

// fused-kernel block layout (waiters only depend on LOWER block ids)
#define NB_FPS    BB                        // 0..7     : FPS
#define GEMM_BASE NB_FPS                    // 8..519   : GEMM (512)
#define NB_GEMM   (ROWS/128)                // 512
#define BN1_BASE  (GEMM_BASE + NB_GEMM)     // 520..775 : bnstat1 (256)
#define NB_BN1    256
#define BN2_BASE  (BN1_BASE + NB_BN1)       // 776      : bnstat2 (1)
#define KNN_BASE  (BN2_BASE + 1)            // 777..    : kNN+gather (2048)
#define NB_KNN    (BB*(MM/8))
#define FUSED_BLOCKS (KNN_BASE + NB_KNN)    // 2825

// ---------------- scratch (static device globals; no allocations) ----------------
__device__ float g_h[(size_t)ROWS*COUT];     // raw h = x @ W^T  (32 MB)
__device__ float g_psum[256*COUT];
__device__ float g_psq [256*COUT];
__device__ float g_scale[COUT];
__device__ float g_shift[COUT];
__device__ int   g_prog[BB];                 // FPS progress       (reset each call)
__device__ int   g_gemm_cnt;                 // finished gemm blks (reset each call)
__device__ int   g_bn1_cnt;                  // finished bn1 blks  (reset each call)
__device__ int   g_scale_ready;              // bn2 published      (reset each call)

// -------- packed f32x2 helpers (sm_100+; per-lane bits == scalar rn ops) --------
#define ADD_F32X2(out, a, b) \
    asm("add.rn.f32x2 %0, %1, %2;" : "=l"(out) : "l"(a), "l"(b))
#define MUL_F32X2(out, a, b) \
    asm("mul.rn.f32x2 %0, %1, %2;" : "=l"(out) : "l"(a), "l"(b))
#define PACK_F32X2(out, lo, hi) \
    asm("mov.b64 %0, {%1, %2};" : "=l"(out) : "f"(lo), "f"(hi))
#define UNPACK_F32X2(lo, hi, in) \
    asm("mov.b64 {%0, %1}, %2;" : "=f"(lo), "=f"(hi) : "l"(in))

#define REDUX_MAX_U32(out, in) \
    asm("redux.sync.max.u32 %0, %1, 0xffffffff;" : "=r"(out) : "r"(in))

__device__ __forceinline__ int ld_acq(const int* p) {
    int v;
    asm volatile("ld.acquire.gpu.global.s32 %0, [%1];" : "=r"(v) : "l"(p));
    return v;
}
__device__ __forceinline__ void st_rel(int* p, int v) {
    asm volatile("st.release.gpu.global.s32 [%0], %1;" :: "l"(p), "r"(v) : "memory");
}
__device__ __forceinline__ unsigned f2key(float d) {
    unsigned u = __float_as_uint(d);
    return u ^ ((u >> 31) ? 0xFFFFFFFFu : 0x80000000u);
}

// =============================== FPS ===============================
// One block per batch (blocks 0..7), 256 threads x 32 points/thread, coords
// in registers (packed f32x2). Distance bits identical to XLA: dx=X+(-lx),
// d=(dx^2+dy^2)+dz^2, separate rn ops — trajectory bit-exact since R3.
// Per iteration (values-only common path; index scan deferred to the winner):
//   math    : packed distances, fmin into MD[32]; VALUE max tree only.
//   warp    : redux.max(val); leaders STS swv (parity); bar1.
//   block   : all warps redux 8 slots -> bval. tid0 resets sidx[(j+1)&1].
//   winner  : threads with bvb==bval (warp-level branch skips other warps)
//             scan their 32 MD for the lowest matching k and
//             atomicMin(sidx[j&1], pbase+k)  -> lowest global index on ties.
//   bar2    : everyone reads sidx[j&1]; coords via broadcast LDS.
// Slot reset safety: sidx[s] reset at iter j (s=(j+1)&1) is after its last
// read (iter j-1, pre-bar1(j)) and before its next write (iter j+1, post-bar1).
__device__ void fps_section(const float* __restrict__ p1, float* __restrict__ p2out,
                            float* sm) {
    float* px = sm; float* py = sm + NN; float* pz = sm + 2*NN;
    __shared__ unsigned swv[2][8];
    __shared__ unsigned sidx[2];
    const int b = blockIdx.x;
    const int tid = threadIdx.x;
    const int lane = tid & 31;
    const int wid  = tid >> 5;
    const float* p = p1 + (size_t)b*NN*3;
    const int pbase = tid*FPS_PT;

    float MD[FPS_PT];
    unsigned long long Xp[FPS_PT/2], Yp[FPS_PT/2], Zp[FPS_PT/2];
    {
        float buf[FPS_PT*3];
        const float4* pv = (const float4*)(p + (size_t)pbase*3);
        #pragma unroll
        for (int i = 0; i < FPS_PT*3/4; i++) {
            float4 v = pv[i];
            buf[i*4+0]=v.x; buf[i*4+1]=v.y; buf[i*4+2]=v.z; buf[i*4+3]=v.w;
        }
        #pragma unroll
        for (int k = 0; k < FPS_PT; k++) {
            MD[k] = 1e10f;
            px[pbase+k]=buf[3*k]; py[pbase+k]=buf[3*k+1]; pz[pbase+k]=buf[3*k+2];
        }
        #pragma unroll
        for (int i = 0; i < FPS_PT/2; i++) {
            PACK_F32X2(Xp[i], buf[6*i+0], buf[6*i+3]);
            PACK_F32X2(Yp[i], buf[6*i+1], buf[6*i+4]);
            PACK_F32X2(Zp[i], buf[6*i+2], buf[6*i+5]);
        }
    }
    if (tid < 2) sidx[tid] = 0xFFFFFFFFu;
    float lx = p[0], ly = p[1], lz = p[2];
    if (tid == 0) {
        size_t o0 = (size_t)b*MM*3;
        p2out[o0+0]=lx; p2out[o0+1]=ly; p2out[o0+2]=lz;
        st_rel(&g_prog[b], 0);
    }
    __syncthreads();

    for (int j = 1; j < MM; j++) {
        float nlx = -lx, nly = -ly, nlz = -lz;
        unsigned long long nlx2, nly2, nlz2;
        PACK_F32X2(nlx2, nlx, nlx);
        PACK_F32X2(nly2, nly, nly);
        PACK_F32X2(nlz2, nlz, nlz);

        #pragma unroll
        for (int i = 0; i < FPS_PT/2; i++) {
            unsigned long long dx, dy, dz, sx, sy, sz, s, d;
            ADD_F32X2(dx, Xp[i], nlx2);          // X + (-lx) == X - lx (bitwise)
            ADD_F32X2(dy, Yp[i], nly2);
            ADD_F32X2(dz, Zp[i], nlz2);
            MUL_F32X2(sx, dx, dx);
            MUL_F32X2(sy, dy, dy);
            MUL_F32X2(sz, dz, dz);
            ADD_F32X2(s,  sx, sy);               // (dx^2+dy^2)
            ADD_F32X2(d,  s,  sz);               // ... + dz^2
            float d0, d1; UNPACK_F32X2(d0, d1, d);
            MD[2*i]   = fminf(MD[2*i],   d0);
            MD[2*i+1] = fminf(MD[2*i+1], d1);
        }

        // thread-local MAX VALUE only (binary tree; index deferred)
        float t[FPS_PT/2];
        #pragma unroll
        for (int k = 0; k < FPS_PT/2; k++) t[k] = fmaxf(MD[2*k], MD[2*k+1]);
        #pragma unroll
        for (int w = FPS_PT/4; w >= 1; w >>= 1)
            #pragma unroll
            for (int k = 0; k < w; k++) t[k] = fmaxf(t[k], t[k+w]);
        float bv = t[0];
        unsigned bvb = __float_as_uint(bv);      // dist >= 0: float order == u32 order

        // warp value max; leaders post; bar1
        unsigned wmax; REDUX_MAX_U32(wmax, bvb);
        if (lane == 0) swv[j & 1][wid] = wmax;
        __syncthreads();                          // bar1

        // block value max (all warps redundantly over 8 leader slots)
        unsigned v  = (lane < 8) ? swv[j & 1][lane] : 0u;
        unsigned bval; REDUX_MAX_U32(bval, v);

        // reset the NEXT parity slot (safe window: post-bar1, pre-bar2)
        if (tid == 0) sidx[(j + 1) & 1] = 0xFFFFFFFFu;

        // only matching threads resolve their index (warp-level skip elsewhere)
        if (bvb == bval) {
            int bi = FPS_PT-1;
            #pragma unroll
            for (int k = FPS_PT-2; k >= 0; k--) if (MD[k] == bval ? true : false) ;
            // (scan below; loop above folded out by compiler)
            bi = FPS_PT-1;
            #pragma unroll
            for (int k = FPS_PT-2; k >= 0; k--) if (__float_as_uint(MD[k]) == bval) bi = k;
            atomicMin(&sidx[j & 1], (unsigned)(pbase + bi));
        }
        __syncthreads();                          // bar2

        unsigned bidx = sidx[j & 1];              // uniform LDS broadcast
        lx = px[bidx]; ly = py[bidx]; lz = pz[bidx];
        if (tid == 0) {
            size_t o2 = (size_t)(b*MM + j)*3;
            p2out[o2] = lx; p2out[o2+1] = ly; p2out[o2+2] = lz;
            st_rel(&g_prog[b], j);
        }
    }
}

// ============ GEMM section (exact fp32, bit-matches cuBLAS SGEMM chain) ============
__device__ void gemm_section(const float* __restrict__ x, const float* __restrict__ W,
                             float* sm) {
    float* xs = sm;                // [128][65] padded
    float* ws = sm + 128*65;       // [64][128] = W^T
    const int tid = threadIdx.x;
    const size_t rb = (size_t)(blockIdx.x - GEMM_BASE) * 128;
    const float* gx = x + rb*CIN;

    for (int i = tid; i < 128*CIN; i += 256) {
        int r = i >> 6, c = i & 63;
        xs[r*65 + c] = gx[i];
    }
    for (int i = tid; i < COUT*CIN; i += 256) {
        int o = i >> 6, c = i & 63;
        ws[c*COUT + o] = W[i];
    }
    __syncthreads();

    const int tx = tid & 15, ty = tid >> 4;
    const int r0 = ty*8, o0 = tx*8;
    float acc[8][8];
    #pragma unroll
    for (int i = 0; i < 8; i++)
        #pragma unroll
        for (int j = 0; j < 8; j++) acc[i][j] = 0.f;

    for (int c = 0; c < CIN; c++) {
        float a[8];
        #pragma unroll
        for (int i = 0; i < 8; i++) a[i] = xs[(r0+i)*65 + c];
        float4 b0 = *(const float4*)&ws[c*COUT + o0];
        float4 b1 = *(const float4*)&ws[c*COUT + o0 + 4];
        float bb[8] = {b0.x,b0.y,b0.z,b0.w,b1.x,b1.y,b1.z,b1.w};
        #pragma unroll
        for (int i = 0; i < 8; i++)
            #pragma unroll
            for (int j = 0; j < 8; j++) acc[i][j] = __fmaf_rn(a[i], bb[j], acc[i][j]);
    }
    #pragma unroll
    for (int i = 0; i < 8; i++) {
        float* out = &g_h[(rb + r0 + i)*COUT + o0];
        *(float4*)out       = make_float4(acc[i][0],acc[i][1],acc[i][2],acc[i][3]);
        *(float4*)(out + 4) = make_float4(acc[i][4],acc[i][5],acc[i][6],acc[i][7]);
    }
    __threadfence();
    __syncthreads();
    if (tid == 0) atomicAdd(&g_gemm_cnt, 1);
}

// ============ bnstat1 section (waits for all gemm blocks) ============
__device__ void bn1_section() {
    __shared__ float cs[128], cq[128];
    const int tid = threadIdx.x;
    if (tid == 0) { while (ld_acq(&g_gemm_cnt) < NB_GEMM) __nanosleep(256); }
    __syncthreads();

    const int blk = blockIdx.x - BN1_BASE;       // 0..255
    const int c = tid & 127;
    const int half = tid >> 7;                   // 0/1
    const float* base = g_h + ((size_t)blk*256 + (size_t)half*128)*COUT;
    float s = 0.f, q = 0.f;
    for (int r = 0; r < 128; r++) {
        float v = base[(size_t)r*COUT + c];
        s += v; q = __fmaf_rn(v, v, q);
    }
    if (half) { cs[c] = s; cq[c] = q; }
    __syncthreads();
    if (!half) {
        g_psum[blk*COUT + c] = s + cs[c];
        g_psq [blk*COUT + c] = q + cq[c];
    }
    __threadfence();
    __syncthreads();
    if (tid == 0) atomicAdd(&g_bn1_cnt, 1);
}

// ============ bnstat2 section (single block; publishes scale_ready) ============
__device__ void bn2_section(const float* __restrict__ gamma, const float* __restrict__ beta) {
    __shared__ double s0[128], q0[128];
    const int tid = threadIdx.x;
    if (tid == 0) { while (ld_acq(&g_bn1_cnt) < NB_BN1) __nanosleep(256); }
    __syncthreads();

    const int c = tid & 127, half = tid >> 7;
    double s = 0.0, q = 0.0;
    for (int i = 0; i < 128; i++) {
        int blk = half*128 + i;
        s += (double)g_psum[blk*COUT + c];
        q += (double)g_psq [blk*COUT + c];
    }
    if (half) { s0[c] = s; q0[c] = q; }
    __syncthreads();
    if (!half) {
        double S = s + s0[c], Q = q + q0[c];
        double mean = S / (double)ROWS;
        double var  = Q / (double)ROWS - mean*mean;
        double inv  = 1.0 / sqrt(var + 1e-5);
        float sc = (float)inv * gamma[c];
        g_scale[c] = sc;
        g_shift[c] = __fmaf_rn(-(float)mean, sc, beta[c]);
    }
    __threadfence();
    __syncthreads();
    if (tid == 0) st_rel(&g_scale_ready, 1);
}

// ============ kNN + inline gather section ============
__device__ void knn_section(const float* __restrict__ p1, const float* __restrict__ p2,
                            float* __restrict__ y, float* sm) {
    float* px = sm; float* py = sm+NN; float* pz = sm+2*NN; float* s1 = sm+3*NN;
    const int tid = threadIdx.x;
    const int q  = blockIdx.x - KNN_BASE;        // 0..2047
    const int b  = q & 7;                        // batch-interleaved
    const int mg = q >> 3;
    const float* p = p1 + (size_t)b*NN*3;

    // independent smem prep overlaps the wait
    for (int i = tid; i < NN*3; i += 256) {
        float v = p[i];
        int pt = i / 3, d = i - pt*3;
        (d == 0 ? px : (d == 1 ? py : pz))[pt] = v;
    }
    __syncthreads();
    for (int i = tid; i < NN; i += 256)
        s1[i] = __fadd_rn(__fadd_rn(__fmul_rn(px[i],px[i]), __fmul_rn(py[i],py[i])), __fmul_rn(pz[i],pz[i]));

    // wait until FPS published query mg*8+7 for this batch (coarse poll)
    if (tid == 0) {
        const int need = mg*8 + 7;
        while (ld_acq(&g_prog[b]) < need) __nanosleep(512);
    }
    __syncthreads();

    const int w = tid >> 5, lane = tid & 31;
    const int m = mg*8 + w;
    const size_t qi = (size_t)b*MM + m;
    // p2 written by FPS blocks this launch -> read via L2 (__ldcg)
    const float qx = __ldcg(&p2[qi*3]);
    const float qy = __ldcg(&p2[qi*3+1]);
    const float qz = __ldcg(&p2[qi*3+2]);
    const float s2 = __fadd_rn(__fadd_rn(__fmul_rn(qx,qx), __fmul_rn(qy,qy)), __fmul_rn(qz,qz));

    const unsigned long long INITK =
        ((unsigned long long)0xFF7FFFFFu << 32) | 0xFFFFFFFFu;
    unsigned long long bk[KNN];
    #pragma unroll
    for (int k = 0; k < KNN; k++) bk[k] = INITK;
    float thr = 3.4e38f;

    for (int i = lane; i < NN; i += 32) {
        float dot = __fmaf_rn(pz[i], qz, __fmaf_rn(py[i], qy, __fmul_rn(px[i], qx)));
        float d   = __fadd_rn(__fsub_rn(s2, __fmul_rn(2.0f, dot)), s1[i]);
        if (d < thr) {   // equal -> keep earlier index (top_k stability)
            unsigned long long nk = ((unsigned long long)f2key(d) << 32) | (unsigned)i;
            unsigned long long mk = 0; int mp = 0;
            #pragma unroll
            for (int k = 0; k < KNN; k++) if (bk[k] > mk) { mk = bk[k]; mp = k; }
            #pragma unroll
            for (int k = 0; k < KNN; k++) if (k == mp) bk[k] = nk;
            mk = 0;
            #pragma unroll
            for (int k = 0; k < KNN; k++) if (bk[k] > mk) mk = bk[k];
            unsigned hv = (unsigned)(mk >> 32);
            hv = (hv & 0x80000000u) ? (hv ^ 0x80000000u) : ~hv;
            thr = __uint_as_float(hv);
        }
    }

    unsigned long long res = 0;
    for (int r = 0; r < KNN; r++) {
        unsigned long long lm = 0xFFFFFFFFFFFFFFFFull;
        #pragma unroll
        for (int k = 0; k < KNN; k++) if (bk[k] < lm) lm = bk[k];
        unsigned long long wm = lm;
        #pragma unroll
        for (int o = 16; o; o >>= 1) {
            unsigned long long t = __shfl_xor_sync(0xffffffffu, wm, o);
            if (t < wm) wm = t;
        }
        if (lm == wm) {
            #pragma unroll
            for (int k = 0; k < KNN; k++) if (bk[k] == wm) bk[k] = 0xFFFFFFFFFFFFFFFFull;
        }
        if (lane == r) res = wm;
    }
    unsigned resi = (unsigned)(res & 0xFFFFFFFFu);   // lane r < 16: r-th neighbor

    // ---- inline gather + BN + ReLU + max (neighbors stay in registers) ----
    if (tid == 0) { while (ld_acq(&g_scale_ready) == 0) __nanosleep(512); }
    __syncthreads();

    const float4 sc = __ldcg((const float4*)&g_scale[lane*4]);
    const float4 sh = __ldcg((const float4*)&g_shift[lane*4]);
    const float* hb = g_h + (size_t)b*NN*COUT;

    float4 acc = make_float4(-3.4e38f,-3.4e38f,-3.4e38f,-3.4e38f);
    #pragma unroll
    for (int k = 0; k < KNN; k++) {
        unsigned n = __shfl_sync(0xffffffffu, resi, k);
        float4 v = *(const float4*)&hb[(size_t)n*COUT + lane*4];
        float f;
        f = fmaxf(__fmaf_rn(v.x, sc.x, sh.x), 0.f); acc.x = fmaxf(acc.x, f);
        f = fmaxf(__fmaf_rn(v.y, sc.y, sh.y), 0.f); acc.y = fmaxf(acc.y, f);
        f = fmaxf(__fmaf_rn(v.z, sc.z, sh.z), 0.f); acc.z = fmaxf(acc.z, f);
        f = fmaxf(__fmaf_rn(v.w, sc.w, sh.w), 0.f); acc.w = fmaxf(acc.w, f);
    }
    *(float4*)&y[qi*COUT + lane*4] = acc;
}

// ================= fused kernel: everything in one launch =================
__global__ void __launch_bounds__(256, 1)
fused_kernel(const float* __restrict__ x, const float* __restrict__ p1,
             const float* __restrict__ W, const float* __restrict__ gamma,
             const float* __restrict__ beta, float* __restrict__ y,
             float* __restrict__ p2out) {
    extern __shared__ float sm[];
    const int bid = blockIdx.x;
    if (bid < NB_FPS)            fps_section(p1, p2out, sm);
    else if (bid < BN1_BASE)     gemm_section(x, W, sm);
    else if (bid < BN2_BASE)     bn1_section();
    else if (bid == BN2_BASE)    bn2_section(gamma, beta);
    else                         knn_section(p1, p2out, y, sm);
}

// ================= per-call state reset (runs before fused, in-stream) =================
__global__ void reset_kernel() {
    const int t = threadIdx.x;
    if (t < BB) g_prog[t] = -1;
    if (t == 8)  g_gemm_cnt = 0;
    if (t == 9)  g_bn1_cnt = 0;
    if (t == 10) g_scale_ready = 0;
}

// =============================== launch ===============================
extern "C" void kernel_launch(void* const* d_in, const int* in_sizes, int n_in,
                              void* d_out, int out_size) {
    const float* x     = (const float*)d_in[0];
    const float* p1    = (const float*)d_in[1];
    const float* W     = (const float*)d_in[2];
    const float* gamma = (const float*)d_in[3];
    const float* beta  = (const float*)d_in[4];
    float* y  = (float*)d_out;
    float* p2 = y + Y_SIZE;

    const int FUSED_SMEM = 4*NN*4;         // 128 KB (knn: 4 arrays; fps: 3; gemm: 66KB)

    cudaFuncSetAttribute(fused_kernel, cudaFuncAttributeMaxDynamicSharedMemorySize, FUSED_SMEM);

    reset_kernel<<<1, 32>>>();
    fused_kernel<<<FUSED_BLOCKS, 256, FUSED_SMEM>>>(x, p1, W, gamma, beta, y, p2);
}